// round 4
// baseline (speedup 1.0000x reference)
#include <cuda_runtime.h>
#include <math.h>

#define B_   64
#define NI_  2048
#define DI_  8
#define NC_  32
#define DC_  16

#define BT   16      // b-tile per block
#define IC   16      // i's per block
// grid = (NI_/IC, B_/BT) = (128, 4) = 512 blocks, 256 threads

// s accumulators for the 3 routing iterations. Zero at module load; k_out
// re-zeroes them each call so graph replays are self-consistent.
__device__ float g_s1[B_ * NC_ * DC_];
__device__ float g_s2[B_ * NC_ * DC_];
__device__ float g_s3[B_ * NC_ * DC_];

// ---------------------------------------------------------------------------
// packed fp32x2 helpers (FFMA2: 2 fp32 FMA per instruction; PTX-only path)
// ---------------------------------------------------------------------------
__device__ __forceinline__ unsigned long long packf2(float lo, float hi) {
    unsigned long long r;
    asm("mov.b64 %0, {%1, %2};" : "=l"(r)
        : "r"(__float_as_uint(lo)), "r"(__float_as_uint(hi)));
    return r;
}
__device__ __forceinline__ void unpackf2(float& lo, float& hi, unsigned long long v) {
    unsigned int a, b;
    asm("mov.b64 {%0, %1}, %2;" : "=r"(a), "=r"(b) : "l"(v));
    lo = __uint_as_float(a); hi = __uint_as_float(b);
}
__device__ __forceinline__ unsigned long long fmaf2(unsigned long long a,
                                                    unsigned long long b,
                                                    unsigned long long c) {
    unsigned long long r;
    asm("fma.rn.f32x2 %0, %1, %2, %3;" : "=l"(r) : "l"(a), "l"(b), "l"(c));
    return r;
}
__device__ __forceinline__ unsigned long long addf2(unsigned long long a,
                                                    unsigned long long b) {
    unsigned long long r;
    asm("add.rn.f32x2 %0, %1, %2;" : "=l"(r) : "l"(a), "l"(b));
    return r;
}

// XOR-swizzled W_sh index: conflict-free for both the transpose store
// (lane=l writes df=4l..4l+3) and the compute read (lane=c, fixed df).
__device__ __forceinline__ int ws(int df, int c) {
    return df * 32 + (c ^ ((df >> 2) & 31));
}

// ---------------------------------------------------------------------------
// k_pass<PASS>: one full pass over (i, b-tile) recomputing u on the fly.
//   PASS 1: s1[b,c,d] += sum_i u   (uniform coupling; 1/NC folded downstream)
//   PASS 2: vr = squash(s1/NC);          s2 += softmax(NI*<u,vr>) * u
//   PASS 3: vr = squash(s1/NC)+squash(s2); s3 += softmax(NI*<u,vr>) * u
// Shared: W_sh 16KB (per-i stage), x_sh 8KB (whole chunk), u_sh 32KB (PASS>=2)
// ---------------------------------------------------------------------------
template <int PASS>
__global__ __launch_bounds__(256) void k_pass(const float* __restrict__ x,
                                              const float* __restrict__ W) {
    extern __shared__ float sm[];
    float* W_sh = sm;            // 4096 floats
    float* x_sh = sm + 4096;     // 2048 floats: [il][f*16 + b]
    float* u_sh = sm + 6144;     // 8192 floats: [b][d*32 + c]  (PASS>=2 only)

    const int t  = threadIdx.x;
    const int w  = t >> 5;       // warp 0..7
    const int c  = t & 31;       // lane = output capsule
    const int i0 = blockIdx.x * IC;
    const int b0 = blockIdx.y * BT;

    // ---- stage x for the whole (b-tile, i-chunk): 2048 floats ----
    // x[b0+b, i0.., :] is a contiguous 128-float run per b.
    #pragma unroll
    for (int r = 0; r < 2; r++) {
        const int lin = t + 256 * r;      // float4 index 0..511
        const int b   = lin >> 5;         // 0..15 (one b per warp-group of 32)
        const int idx = lin & 31;         // float4 within the 128-float run
        const float4 v = *(const float4*)(x + ((b0 + b) * NI_ + i0) * DI_ + idx * 4);
        const int il = idx >> 1, fo = (idx & 1) * 4;
        x_sh[il * 128 + (fo + 0) * 16 + b] = v.x;
        x_sh[il * 128 + (fo + 1) * 16 + b] = v.y;
        x_sh[il * 128 + (fo + 2) * 16 + b] = v.z;
        x_sh[il * 128 + (fo + 3) * 16 + b] = v.w;
    }

    // ---- prologue: routing vector vr (packed over d-pairs), PASS>=2 ----
    unsigned long long vrP[2][8];
    unsigned long long sP[2][8];          // packed s accumulators (PASS>=2)
    unsigned long long sPd0[8], sPd1[8];  // packed over b-pairs (PASS==1)
    if (PASS == 1) {
        #pragma unroll
        for (int p = 0; p < 8; p++) { sPd0[p] = 0ull; sPd1[p] = 0ull; }
    } else {
        #pragma unroll
        for (int bl = 0; bl < 2; bl++) {
            const int bb = b0 + 2 * w + bl;
            float vr[DC_];
            {   // v1 = squash(s1 / NC)
                const float4* p1 = (const float4*)(g_s1 + (bb * NC_ + c) * DC_);
                float sv[DC_]; float sq = 0.0f;
                #pragma unroll
                for (int q = 0; q < 4; q++) {
                    const float4 v = p1[q];
                    sv[4*q+0] = v.x * (1.0f/NC_); sv[4*q+1] = v.y * (1.0f/NC_);
                    sv[4*q+2] = v.z * (1.0f/NC_); sv[4*q+3] = v.w * (1.0f/NC_);
                }
                #pragma unroll
                for (int d = 0; d < DC_; d++) sq += sv[d] * sv[d];
                const float f2 = (sq / (1.0f + sq)) * rsqrtf(sq + 1e-7f);
                #pragma unroll
                for (int d = 0; d < DC_; d++) vr[d] = sv[d] * f2;
            }
            if (PASS == 3) {   // vr += squash(s2)
                const float4* p2 = (const float4*)(g_s2 + (bb * NC_ + c) * DC_);
                float sv[DC_]; float sq = 0.0f;
                #pragma unroll
                for (int q = 0; q < 4; q++) {
                    const float4 v = p2[q];
                    sv[4*q+0] = v.x; sv[4*q+1] = v.y; sv[4*q+2] = v.z; sv[4*q+3] = v.w;
                }
                #pragma unroll
                for (int d = 0; d < DC_; d++) sq += sv[d] * sv[d];
                const float f2 = (sq / (1.0f + sq)) * rsqrtf(sq + 1e-7f);
                #pragma unroll
                for (int d = 0; d < DC_; d++) vr[d] += sv[d] * f2;
            }
            #pragma unroll
            for (int dd = 0; dd < 8; dd++)
                vrP[bl][dd] = packf2(vr[2*dd], vr[2*dd+1]);
            #pragma unroll
            for (int dd = 0; dd < 8; dd++) sP[bl][dd] = 0ull;
        }
    }

    // ---- main loop over i's ----
    for (int il = 0; il < IC; il++) {
        const int i = i0 + il;

        // stage W[:, i, :, :] -> W_sh[ws(df, c')]  (transpose, conflict-free)
        #pragma unroll
        for (int cc = 0; cc < 4; cc++) {
            const int cw = w * 4 + cc;
            const float4 v = *(const float4*)(W + (cw * NI_ + i) * (DC_ * DI_) + c * 4);
            W_sh[ws(4*c + 0, cw)] = v.x;
            W_sh[ws(4*c + 1, cw)] = v.y;
            W_sh[ws(4*c + 2, cw)] = v.z;
            W_sh[ws(4*c + 3, cw)] = v.w;
        }
        __syncthreads();

        // compute u for this i: warp w -> d0=w, d1=w+8; packed over b-pairs
        const int d0 = w, d1 = w + 8;
        unsigned long long W0p[8], W1p[8];
        #pragma unroll
        for (int f = 0; f < 8; f++) {
            const float a0 = W_sh[ws(d0 * 8 + f, c)];
            const float a1 = W_sh[ws(d1 * 8 + f, c)];
            W0p[f] = packf2(a0, a0);
            W1p[f] = packf2(a1, a1);
        }
        #pragma unroll
        for (int p = 0; p < 8; p++) {
            unsigned long long acc0 = 0ull, acc1 = 0ull;
            #pragma unroll
            for (int f = 0; f < 8; f++) {
                const unsigned long long xp =
                    *(const unsigned long long*)&x_sh[il * 128 + f * 16 + 2 * p];
                acc0 = fmaf2(W0p[f], xp, acc0);
                acc1 = fmaf2(W1p[f], xp, acc1);
            }
            if (PASS == 1) {
                sPd0[p] = addf2(sPd0[p], acc0);
                sPd1[p] = addf2(sPd1[p], acc1);
            } else {
                float lo, hi;
                unpackf2(lo, hi, acc0);
                u_sh[(2*p  ) * 512 + d0 * 32 + c] = lo;
                u_sh[(2*p+1) * 512 + d0 * 32 + c] = hi;
                unpackf2(lo, hi, acc1);
                u_sh[(2*p  ) * 512 + d1 * 32 + c] = lo;
                u_sh[(2*p+1) * 512 + d1 * 32 + c] = hi;
            }
        }
        __syncthreads();

        if (PASS >= 2) {
            // route: warp w handles local b = 2w, 2w+1; lane = c
            #pragma unroll
            for (int bl = 0; bl < 2; bl++) {
                const int bL = 2 * w + bl;
                unsigned long long up[8];
                #pragma unroll
                for (int dd = 0; dd < 8; dd++) {
                    const float lo = u_sh[bL * 512 + (2*dd  ) * 32 + c];
                    const float hi = u_sh[bL * 512 + (2*dd+1) * 32 + c];
                    up[dd] = packf2(lo, hi);
                }
                unsigned long long aP = 0ull;
                #pragma unroll
                for (int dd = 0; dd < 8; dd++) aP = fmaf2(up[dd], vrP[bl][dd], aP);
                float alo, ahi; unpackf2(alo, ahi, aP);
                const float logit = (float)NI_ * (alo + ahi);

                float m = logit;
                #pragma unroll
                for (int off = 16; off > 0; off >>= 1)
                    m = fmaxf(m, __shfl_xor_sync(0xFFFFFFFFu, m, off));
                const float e = __expf(logit - m);
                float ssum = e;
                #pragma unroll
                for (int off = 16; off > 0; off >>= 1)
                    ssum += __shfl_xor_sync(0xFFFFFFFFu, ssum, off);
                const float coef = e / ssum;

                const unsigned long long coefP = packf2(coef, coef);
                #pragma unroll
                for (int dd = 0; dd < 8; dd++)
                    sP[bl][dd] = fmaf2(coefP, up[dd], sP[bl][dd]);
            }
        }
        // route reads of u_sh are protected from next-i compute writes by the
        // __syncthreads() after the next W stage.
    }

    // ---- epilogue: per-block partials -> global accumulator ----
    if (PASS == 1) {
        #pragma unroll
        for (int p = 0; p < 8; p++) {
            float lo, hi;
            unpackf2(lo, hi, sPd0[p]);
            atomicAdd(&g_s1[((b0 + 2*p    ) * NC_ + c) * DC_ + w    ], lo);
            atomicAdd(&g_s1[((b0 + 2*p + 1) * NC_ + c) * DC_ + w    ], hi);
            unpackf2(lo, hi, sPd1[p]);
            atomicAdd(&g_s1[((b0 + 2*p    ) * NC_ + c) * DC_ + w + 8], lo);
            atomicAdd(&g_s1[((b0 + 2*p + 1) * NC_ + c) * DC_ + w + 8], hi);
        }
    } else {
        float* gs = (PASS == 2) ? g_s2 : g_s3;
        #pragma unroll
        for (int bl = 0; bl < 2; bl++) {
            const int bb = b0 + 2 * w + bl;
            #pragma unroll
            for (int dd = 0; dd < 8; dd++) {
                float lo, hi;
                unpackf2(lo, hi, sP[bl][dd]);
                atomicAdd(&gs[(bb * NC_ + c) * DC_ + 2*dd    ], lo);
                atomicAdd(&gs[(bb * NC_ + c) * DC_ + 2*dd + 1], hi);
            }
        }
    }
}

// ---------------------------------------------------------------------------
// k_out: v3 = squash(s3) -> out; then zero all accumulators for next replay.
// ---------------------------------------------------------------------------
__global__ void k_out(float* __restrict__ out) {
    const int t = blockIdx.x * blockDim.x + threadIdx.x;
    if (t >= B_ * NC_) return;
    float sv[DC_]; float sq = 0.0f;
    const float4* p3 = (const float4*)(g_s3 + t * DC_);
    #pragma unroll
    for (int q = 0; q < 4; q++) {
        const float4 v = p3[q];
        sv[4*q+0] = v.x; sv[4*q+1] = v.y; sv[4*q+2] = v.z; sv[4*q+3] = v.w;
    }
    #pragma unroll
    for (int d = 0; d < DC_; d++) sq += sv[d] * sv[d];
    const float f2 = (sq / (1.0f + sq)) * rsqrtf(sq + 1e-7f);
    #pragma unroll
    for (int d = 0; d < DC_; d++) out[t * DC_ + d] = sv[d] * f2;
    #pragma unroll
    for (int d = 0; d < DC_; d++) {
        g_s1[t * DC_ + d] = 0.0f;
        g_s2[t * DC_ + d] = 0.0f;
        g_s3[t * DC_ + d] = 0.0f;
    }
}

// ---------------------------------------------------------------------------
extern "C" void kernel_launch(void* const* d_in, const int* in_sizes, int n_in,
                              void* d_out, int out_size) {
    const float* x = (const float*)d_in[0];
    const float* W = (const float*)d_in[1];
    if (n_in >= 2 && in_sizes[0] == NC_ * NI_ * DC_ * DI_) {  // defensive order swap
        const float* tmp = x; x = W; W = tmp;
    }
    float* out = (float*)d_out;

    const int SM1  = (4096 + 2048) * 4;          // 24 KB (no u_sh)
    const int SM23 = (4096 + 2048 + 8192) * 4;   // 56 KB
    cudaFuncSetAttribute(k_pass<1>, cudaFuncAttributeMaxDynamicSharedMemorySize, SM1);
    cudaFuncSetAttribute(k_pass<2>, cudaFuncAttributeMaxDynamicSharedMemorySize, SM23);
    cudaFuncSetAttribute(k_pass<3>, cudaFuncAttributeMaxDynamicSharedMemorySize, SM23);

    const dim3 grid(NI_ / IC, B_ / BT);
    k_pass<1><<<grid, 256, SM1 >>>(x, W);
    k_pass<2><<<grid, 256, SM23>>>(x, W);
    k_pass<3><<<grid, 256, SM23>>>(x, W);
    k_out<<<(B_ * NC_ + 255) / 256, 256>>>(out);
}

// round 5
// speedup vs baseline: 1.6602x; 1.6602x over previous
#include <cuda_runtime.h>
#include <math.h>

#define B_   64
#define NI_  2048
#define DI_  8
#define NC_  32
#define DC_  16

#define ICU  16      // i's per k_u block
#define BTU  16      // b's per k_u block
#define CHR  16      // i-chunks per b in route

// u layout: [b][i][d4][c][4] -> float4 index = (b*NI+i)*128 + d4*32 + c
__device__ __align__(16) float g_u[B_*NI_*DC_*NC_];   // 256 MB
__device__ __align__(16) float g_s1[B_*NC_*DC_];      // sum_i u (uniform pass)
__device__ __align__(16) float g_s2[B_*NC_*DC_];      // iter-2 s
__device__ __align__(16) float g_s3[B_*NC_*DC_];      // iter-3 s
// all accumulators: zero at load; k_out re-zeroes for graph-replay invariance.

// ---- packed fp32x2 helpers (FFMA2 is PTX-only) ----
__device__ __forceinline__ unsigned long long packf2(float lo, float hi) {
    unsigned long long r;
    asm("mov.b64 %0, {%1, %2};" : "=l"(r)
        : "r"(__float_as_uint(lo)), "r"(__float_as_uint(hi)));
    return r;
}
__device__ __forceinline__ void unpackf2(float& lo, float& hi, unsigned long long v) {
    unsigned int a, b;
    asm("mov.b64 {%0, %1}, %2;" : "=r"(a), "=r"(b) : "l"(v));
    lo = __uint_as_float(a); hi = __uint_as_float(b);
}
__device__ __forceinline__ unsigned long long fmaf2(unsigned long long a,
                                                    unsigned long long b,
                                                    unsigned long long c) {
    unsigned long long r;
    asm("fma.rn.f32x2 %0, %1, %2, %3;" : "=l"(r) : "l"(a), "l"(b), "l"(c));
    return r;
}
__device__ __forceinline__ unsigned long long addf2(unsigned long long a,
                                                    unsigned long long b) {
    unsigned long long r;
    asm("add.rn.f32x2 %0, %1, %2;" : "=l"(r) : "l"(a), "l"(b));
    return r;
}

// XOR-swizzled W_sh index: conflict-free for both transpose store and lane=c read.
__device__ __forceinline__ int ws(int df, int c) {
    return df * 32 + (c ^ ((df >> 2) & 31));
}

// ---------------------------------------------------------------------------
// k_u: materialize u (float4 route layout) AND accumulate s1 = sum_i u.
// grid (NI/ICU, B/BTU) = (128, 4), 256 threads. Warp w -> d pair (2w, 2w+1).
// ---------------------------------------------------------------------------
__global__ __launch_bounds__(256) void k_u(const float* __restrict__ x,
                                           const float* __restrict__ W) {
    __shared__ __align__(16) float W_sh[4096];   // per-i W stage (swizzled)
    __shared__ __align__(16) float x_sh[2048];   // [il][f*16 + bl]

    const int t = threadIdx.x, w = t >> 5, c = t & 31;
    const int i0 = blockIdx.x * ICU;
    const int b0 = blockIdx.y * BTU;

    // stage x: x[b0+bl, i0.., :] is 128 contiguous floats per bl
    #pragma unroll
    for (int r = 0; r < 2; r++) {
        const int lin = t + 256 * r;            // float4 idx 0..511
        const int bl = lin >> 5, q = lin & 31;  // il = q>>1, f0 = (q&1)*4
        const float4 v = *(const float4*)(x + ((b0 + bl) * NI_ + i0) * DI_ + q * 4);
        const int il = q >> 1, f0 = (q & 1) * 4;
        x_sh[il * 128 + (f0 + 0) * 16 + bl] = v.x;
        x_sh[il * 128 + (f0 + 1) * 16 + bl] = v.y;
        x_sh[il * 128 + (f0 + 2) * 16 + bl] = v.z;
        x_sh[il * 128 + (f0 + 3) * 16 + bl] = v.w;
    }

    unsigned long long sP0[8], sP1[8];   // s1 partials, packed over b-pairs
    #pragma unroll
    for (int p = 0; p < 8; p++) { sP0[p] = 0ull; sP1[p] = 0ull; }

    const int d0 = 2 * w, d1 = 2 * w + 1;
    const int d4 = w >> 1, comp = (w & 1) * 2;   // float4 quarter + component

    for (int il = 0; il < ICU; il++) {
        const int i = i0 + il;

        // stage W[:, i, :, :] transposed+swizzled (coalesced 128B row segments)
        #pragma unroll
        for (int cc = 0; cc < 4; cc++) {
            const int cw = w * 4 + cc;
            const float4 v = *(const float4*)(W + (cw * NI_ + i) * (DC_ * DI_) + c * 4);
            W_sh[ws(4 * c + 0, cw)] = v.x;
            W_sh[ws(4 * c + 1, cw)] = v.y;
            W_sh[ws(4 * c + 2, cw)] = v.z;
            W_sh[ws(4 * c + 3, cw)] = v.w;
        }
        __syncthreads();

        unsigned long long W0p[8], W1p[8];
        #pragma unroll
        for (int f = 0; f < 8; f++) {
            const float a0 = W_sh[ws(d0 * 8 + f, c)];
            const float a1 = W_sh[ws(d1 * 8 + f, c)];
            W0p[f] = packf2(a0, a0);
            W1p[f] = packf2(a1, a1);
        }
        #pragma unroll
        for (int p = 0; p < 8; p++) {
            unsigned long long acc0 = 0ull, acc1 = 0ull;
            #pragma unroll
            for (int f = 0; f < 8; f++) {
                const unsigned long long xp =
                    *(const unsigned long long*)&x_sh[il * 128 + f * 16 + 2 * p];
                acc0 = fmaf2(W0p[f], xp, acc0);   // (d0; b=2p, 2p+1)
                acc1 = fmaf2(W1p[f], xp, acc1);   // (d1; b=2p, 2p+1)
            }
            float lo0, hi0, lo1, hi1;
            unpackf2(lo0, hi0, acc0);
            unpackf2(lo1, hi1, acc1);
            const int e0 = (((b0 + 2*p    ) * NI_ + i) * 128 + d4 * 32 + c) * 4 + comp;
            const int e1 = (((b0 + 2*p + 1) * NI_ + i) * 128 + d4 * 32 + c) * 4 + comp;
            *(float2*)(g_u + e0) = make_float2(lo0, lo1);   // (d0, d1) for b=2p
            *(float2*)(g_u + e1) = make_float2(hi0, hi1);   // (d0, d1) for b=2p+1
            sP0[p] = addf2(sP0[p], acc0);
            sP1[p] = addf2(sP1[p], acc1);
        }
        __syncthreads();   // protect W_sh before next stage
    }

    // s1 epilogue: each (b,c,d) owned by exactly one thread in this block
    #pragma unroll
    for (int p = 0; p < 8; p++) {
        float lo, hi;
        unpackf2(lo, hi, sP0[p]);
        atomicAdd(&g_s1[((b0 + 2*p    ) * NC_ + c) * DC_ + d0], lo);
        atomicAdd(&g_s1[((b0 + 2*p + 1) * NC_ + c) * DC_ + d0], hi);
        unpackf2(lo, hi, sP1[p]);
        atomicAdd(&g_s1[((b0 + 2*p    ) * NC_ + c) * DC_ + d1], lo);
        atomicAdd(&g_s1[((b0 + 2*p + 1) * NC_ + c) * DC_ + d1], hi);
    }
}

// ---------------------------------------------------------------------------
// k_route<PASS>: fused squash-prologue + agree -> softmax -> s-accumulate.
//   PASS 2: vr = squash(s1/NC);              s2 += softmax(NI*<u,vr>) * u
//   PASS 3: vr = squash(s1/NC)+squash(s2);   s3 += softmax(NI*<u,vr>) * u
// ---------------------------------------------------------------------------
template <int PASS>
__global__ __launch_bounds__(256) void k_route() {
    __shared__ float s_sh[8 * 512];
    const int chunk = blockIdx.x;     // 0..CHR-1
    const int b     = blockIdx.y;     // 0..63
    const int w = threadIdx.x >> 5, c = threadIdx.x & 31;
    const int IPW = NI_ / CHR / 8;    // 16
    const int i0 = chunk * (NI_ / CHR) + w * IPW;

    // prologue: vr for (b, c)
    float vr[DC_];
    {
        const float4* p1 = (const float4*)(g_s1 + (b * NC_ + c) * DC_);
        float sv[DC_]; float sq = 0.0f;
        #pragma unroll
        for (int q = 0; q < 4; q++) {
            const float4 v = p1[q];
            sv[4*q+0] = v.x * (1.0f/NC_); sv[4*q+1] = v.y * (1.0f/NC_);
            sv[4*q+2] = v.z * (1.0f/NC_); sv[4*q+3] = v.w * (1.0f/NC_);
        }
        #pragma unroll
        for (int d = 0; d < DC_; d++) sq += sv[d] * sv[d];
        const float f2 = (sq / (1.0f + sq)) * rsqrtf(sq + 1e-7f);
        #pragma unroll
        for (int d = 0; d < DC_; d++) vr[d] = sv[d] * f2;
    }
    if (PASS == 3) {
        const float4* p2 = (const float4*)(g_s2 + (b * NC_ + c) * DC_);
        float sv[DC_]; float sq = 0.0f;
        #pragma unroll
        for (int q = 0; q < 4; q++) {
            const float4 v = p2[q];
            sv[4*q+0] = v.x; sv[4*q+1] = v.y; sv[4*q+2] = v.z; sv[4*q+3] = v.w;
        }
        #pragma unroll
        for (int d = 0; d < DC_; d++) sq += sv[d] * sv[d];
        const float f2 = (sq / (1.0f + sq)) * rsqrtf(sq + 1e-7f);
        #pragma unroll
        for (int d = 0; d < DC_; d++) vr[d] += sv[d] * f2;
    }
    const float4 vr0 = make_float4(vr[0],  vr[1],  vr[2],  vr[3]);
    const float4 vr1 = make_float4(vr[4],  vr[5],  vr[6],  vr[7]);
    const float4 vr2 = make_float4(vr[8],  vr[9],  vr[10], vr[11]);
    const float4 vr3 = make_float4(vr[12], vr[13], vr[14], vr[15]);

    float4 s0 = {0,0,0,0}, s1 = {0,0,0,0}, s2 = {0,0,0,0}, s3 = {0,0,0,0};
    const float4* __restrict__ u4 = (const float4*)g_u;

    #pragma unroll 2
    for (int ii = 0; ii < IPW; ii++) {
        const int base = (b * NI_ + (i0 + ii)) * 128 + c;
        const float4 u0 = u4[base];
        const float4 u1 = u4[base + 32];
        const float4 u2 = u4[base + 64];
        const float4 u3 = u4[base + 96];

        float a = u0.x*vr0.x + u0.y*vr0.y + u0.z*vr0.z + u0.w*vr0.w
                + u1.x*vr1.x + u1.y*vr1.y + u1.z*vr1.z + u1.w*vr1.w
                + u2.x*vr2.x + u2.y*vr2.y + u2.z*vr2.z + u2.w*vr2.w
                + u3.x*vr3.x + u3.y*vr3.y + u3.z*vr3.z + u3.w*vr3.w;
        const float logit = (float)NI_ * a;

        float m = logit;
        #pragma unroll
        for (int off = 16; off > 0; off >>= 1)
            m = fmaxf(m, __shfl_xor_sync(0xFFFFFFFFu, m, off));
        const float e = __expf(logit - m);
        float ssum = e;
        #pragma unroll
        for (int off = 16; off > 0; off >>= 1)
            ssum += __shfl_xor_sync(0xFFFFFFFFu, ssum, off);
        const float coef = e / ssum;

        s0.x = fmaf(coef, u0.x, s0.x); s0.y = fmaf(coef, u0.y, s0.y);
        s0.z = fmaf(coef, u0.z, s0.z); s0.w = fmaf(coef, u0.w, s0.w);
        s1.x = fmaf(coef, u1.x, s1.x); s1.y = fmaf(coef, u1.y, s1.y);
        s1.z = fmaf(coef, u1.z, s1.z); s1.w = fmaf(coef, u1.w, s1.w);
        s2.x = fmaf(coef, u2.x, s2.x); s2.y = fmaf(coef, u2.y, s2.y);
        s2.z = fmaf(coef, u2.z, s2.z); s2.w = fmaf(coef, u2.w, s2.w);
        s3.x = fmaf(coef, u3.x, s3.x); s3.y = fmaf(coef, u3.y, s3.y);
        s3.z = fmaf(coef, u3.z, s3.z); s3.w = fmaf(coef, u3.w, s3.w);
    }

    const int sb = w * 512;
    s_sh[sb +  0*32 + c] = s0.x; s_sh[sb +  1*32 + c] = s0.y;
    s_sh[sb +  2*32 + c] = s0.z; s_sh[sb +  3*32 + c] = s0.w;
    s_sh[sb +  4*32 + c] = s1.x; s_sh[sb +  5*32 + c] = s1.y;
    s_sh[sb +  6*32 + c] = s1.z; s_sh[sb +  7*32 + c] = s1.w;
    s_sh[sb +  8*32 + c] = s2.x; s_sh[sb +  9*32 + c] = s2.y;
    s_sh[sb + 10*32 + c] = s2.z; s_sh[sb + 11*32 + c] = s2.w;
    s_sh[sb + 12*32 + c] = s3.x; s_sh[sb + 13*32 + c] = s3.y;
    s_sh[sb + 14*32 + c] = s3.z; s_sh[sb + 15*32 + c] = s3.w;
    __syncthreads();

    float* gs = (PASS == 2) ? g_s2 : g_s3;
    #pragma unroll
    for (int r = 0; r < 2; r++) {
        const int idx = threadIdx.x + r * 256;   // d*32 + c
        float acc = 0.0f;
        #pragma unroll
        for (int ww = 0; ww < 8; ww++) acc += s_sh[ww * 512 + idx];
        const int cc = idx & 31, dd = idx >> 5;
        atomicAdd(&gs[(b * NC_ + cc) * DC_ + dd], acc);
    }
}

// ---------------------------------------------------------------------------
// k_out: v3 = squash(s3) -> out; zero all accumulators for next replay.
// ---------------------------------------------------------------------------
__global__ void k_out(float* __restrict__ out) {
    const int t = blockIdx.x * blockDim.x + threadIdx.x;
    if (t >= B_ * NC_) return;
    float sv[DC_]; float sq = 0.0f;
    const float4* p3 = (const float4*)(g_s3 + t * DC_);
    #pragma unroll
    for (int q = 0; q < 4; q++) {
        const float4 v = p3[q];
        sv[4*q+0] = v.x; sv[4*q+1] = v.y; sv[4*q+2] = v.z; sv[4*q+3] = v.w;
    }
    #pragma unroll
    for (int d = 0; d < DC_; d++) sq += sv[d] * sv[d];
    const float f2 = (sq / (1.0f + sq)) * rsqrtf(sq + 1e-7f);
    #pragma unroll
    for (int d = 0; d < DC_; d++) out[t * DC_ + d] = sv[d] * f2;
    #pragma unroll
    for (int d = 0; d < DC_; d++) {
        g_s1[t * DC_ + d] = 0.0f;
        g_s2[t * DC_ + d] = 0.0f;
        g_s3[t * DC_ + d] = 0.0f;
    }
}

// ---------------------------------------------------------------------------
extern "C" void kernel_launch(void* const* d_in, const int* in_sizes, int n_in,
                              void* d_out, int out_size) {
    const float* x = (const float*)d_in[0];
    const float* W = (const float*)d_in[1];
    if (n_in >= 2 && in_sizes[0] == NC_ * NI_ * DC_ * DI_) {  // defensive order swap
        const float* tmp = x; x = W; W = tmp;
    }
    float* out = (float*)d_out;

    k_u<<<dim3(NI_ / ICU, B_ / BTU), 256>>>(x, W);   // u + s1 in one pass
    k_route<2><<<dim3(CHR, B_), 256>>>();            // s2
    k_route<3><<<dim3(CHR, B_), 256>>>();            // s3
    k_out<<<(B_ * NC_ + 255) / 256, 256>>>(out);     // squash + reset
}